// round 2
// baseline (speedup 1.0000x reference)
#include <cuda_runtime.h>
#include <cstdint>

// Problem constants (fixed by the reference)
#define BB 8
#define NN 10000
#define FF 256
#define HH 128
#define EE 320000

// Scratch for xw = dropout(x) @ W : [B, N, H] = 8*10000*128 floats = 41 MB
__device__ float g_xw[(size_t)BB * NN * HH];

// ---------------------------------------------------------------------------
// Kernel 0: zero the output (harness poisons it with 0xAA)
// ---------------------------------------------------------------------------
__global__ __launch_bounds__(256) void zero_kernel(float4* __restrict__ out) {
    size_t i = (size_t)blockIdx.x * blockDim.x + threadIdx.x;
    out[i] = make_float4(0.f, 0.f, 0.f, 0.f);
}

// ---------------------------------------------------------------------------
// Kernel 1: fused dropout + SGEMM
//   A = (drop_u > 0.5 ? 2*x : 0)   [M=80000, K=256]
//   B = weight                     [K=256,  H=128]
//   C = g_xw                       [M, 128]
// Tile: 128 (M) x 128 (H), K-step 8, 256 threads, 8x8 per-thread microtile.
// Register-prefetch software pipeline over the single smem buffer.
// ---------------------------------------------------------------------------
__global__ __launch_bounds__(256) void gemm_dropout_kernel(
    const float* __restrict__ X, const float* __restrict__ U,
    const float* __restrict__ W, float* __restrict__ XW)
{
    __shared__ float As[8][128];
    __shared__ float Bs[8][128];

    const int t  = threadIdx.x;
    const int tx = t & 15;          // 0..15 -> H columns tx*8
    const int ty = t >> 4;          // 0..15 -> M rows    ty*8
    const int mBase = blockIdx.x * 128;

    // A-load mapping: 128 rows x 8 k per tile = 256 float4 (x) + 256 float4 (u)
    const int lrow = t >> 1;        // 0..127
    const int lkq  = t & 1;         // which float4 of the 8-wide k slice
    // B-load mapping: 8 k x 128 h = 256 float4
    const int bk = t >> 5;          // 0..7
    const int bh = t & 31;          // 0..31 -> float4 column

    const float4* __restrict__ X4 = (const float4*)X;
    const float4* __restrict__ U4 = (const float4*)U;
    const float4* __restrict__ W4 = (const float4*)W;

    const size_t aRowBase = (size_t)(mBase + lrow) * (FF / 4); // float4 index of row start

    float acc[8][8];
#pragma unroll
    for (int i = 0; i < 8; ++i)
#pragma unroll
        for (int j = 0; j < 8; ++j) acc[i][j] = 0.f;

    // prefetch tile 0
    float4 xv = X4[aRowBase + 0 * 2 + lkq];
    float4 uv = U4[aRowBase + 0 * 2 + lkq];
    float4 wv = W4[(0 * 8 + bk) * 32 + bh];

    const int KT = FF / 8;  // 32 k-tiles
    for (int kt = 0; kt < KT; ++kt) {
        // commit prefetched regs to smem (apply dropout to A)
        float4 av;
        av.x = (uv.x > 0.5f) ? 2.0f * xv.x : 0.0f;
        av.y = (uv.y > 0.5f) ? 2.0f * xv.y : 0.0f;
        av.z = (uv.z > 0.5f) ? 2.0f * xv.z : 0.0f;
        av.w = (uv.w > 0.5f) ? 2.0f * xv.w : 0.0f;
        As[lkq * 4 + 0][lrow] = av.x;
        As[lkq * 4 + 1][lrow] = av.y;
        As[lkq * 4 + 2][lrow] = av.z;
        As[lkq * 4 + 3][lrow] = av.w;
        *(float4*)&Bs[bk][bh * 4] = wv;
        __syncthreads();

        // prefetch next tile while computing
        if (kt + 1 < KT) {
            xv = X4[aRowBase + (kt + 1) * 2 + lkq];
            uv = U4[aRowBase + (kt + 1) * 2 + lkq];
            wv = W4[((kt + 1) * 8 + bk) * 32 + bh];
        }

#pragma unroll
        for (int kk = 0; kk < 8; ++kk) {
            float a[8], b[8];
            *(float4*)&a[0] = *(const float4*)&As[kk][ty * 8 + 0];
            *(float4*)&a[4] = *(const float4*)&As[kk][ty * 8 + 4];
            *(float4*)&b[0] = *(const float4*)&Bs[kk][tx * 8 + 0];
            *(float4*)&b[4] = *(const float4*)&Bs[kk][tx * 8 + 4];
#pragma unroll
            for (int i = 0; i < 8; ++i)
#pragma unroll
                for (int j = 0; j < 8; ++j)
                    acc[i][j] += a[i] * b[j];
        }
        __syncthreads();
    }

    // epilogue
#pragma unroll
    for (int i = 0; i < 8; ++i) {
        size_t m = (size_t)(mBase + ty * 8 + i);
        float4 o0 = make_float4(acc[i][0], acc[i][1], acc[i][2], acc[i][3]);
        float4 o1 = make_float4(acc[i][4], acc[i][5], acc[i][6], acc[i][7]);
        *(float4*)&XW[m * HH + tx * 8 + 0] = o0;
        *(float4*)&XW[m * HH + tx * 8 + 4] = o1;
    }
}

// ---------------------------------------------------------------------------
// Kernel 2: SpMM scatter with vector atomics.
//   out[b, rows[e], :] += vals[e] * xw[b, cols[e], :]
// 4 edges per warp, gather-then-reduce to maximize MLP.
// NOTE: rows/cols are int32 on device (JAX x64 disabled downcasts int64).
// ---------------------------------------------------------------------------
__device__ __forceinline__ void red_add_v4(float* dst, float4 v) {
    asm volatile("red.global.add.v4.f32 [%0], {%1, %2, %3, %4};"
                 :: "l"(dst), "f"(v.x), "f"(v.y), "f"(v.z), "f"(v.w)
                 : "memory");
}

__global__ __launch_bounds__(256) void spmm_kernel(
    const int* __restrict__ rows, const int* __restrict__ cols,
    const float* __restrict__ vals, const float* __restrict__ xw,
    float* __restrict__ out)
{
    const int EPW = 4; // edges per warp
    const int warp = (blockIdx.x * blockDim.x + threadIdx.x) >> 5;
    const int lane = threadIdx.x & 31;

    long long e0 = (long long)warp * EPW;

    // load edge metadata + gather first, then all reductions (maximize MLP)
    float4 contrib[EPW];
    float* dst[EPW];
#pragma unroll
    for (int i = 0; i < EPW; ++i) {
        long long e = e0 + i;                   // grid sized exactly: no bounds check
        int b = (int)(e / EE);
        int r = __ldg(&rows[e]);
        int c = __ldg(&cols[e]);
        float v = __ldg(&vals[e]);
        const float4* src = (const float4*)(xw + ((size_t)b * NN + c) * HH) + lane;
        float4 s = __ldg(src);
        contrib[i] = make_float4(v * s.x, v * s.y, v * s.z, v * s.w);
        dst[i] = out + ((size_t)b * NN + r) * HH + lane * 4;
    }
#pragma unroll
    for (int i = 0; i < EPW; ++i)
        red_add_v4(dst[i], contrib[i]);
}

// ---------------------------------------------------------------------------
// launch
// ---------------------------------------------------------------------------
extern "C" void kernel_launch(void* const* d_in, const int* in_sizes, int n_in,
                              void* d_out, int out_size) {
    const float* x    = (const float*)d_in[0];      // [8,10000,256] f32
    const float* u    = (const float*)d_in[1];      // [8,10000,256] f32
    const int*   rows = (const int*)d_in[2];        // [8,320000] int32 (x64-off downcast)
    const int*   cols = (const int*)d_in[3];        // [8,320000] int32
    const float* vals = (const float*)d_in[4];      // [8,320000] f32
    const float* w    = (const float*)d_in[5];      // [256,128] f32
    float* out = (float*)d_out;                     // [8,10000,128] f32

    float* xw;
    cudaGetSymbolAddress((void**)&xw, g_xw);

    // 0) zero the output: 10.24M floats / 4 / 256
    zero_kernel<<<(BB * NN * HH / 4) / 256, 256>>>((float4*)out);

    // 1) fused dropout + GEMM: M=80000 rows -> 625 tiles of 128
    gemm_dropout_kernel<<<(BB * NN) / 128, 256>>>(x, u, w, xw);

    // 2) SpMM scatter: 2.56M edges, 4/warp, 8 warps/block -> 80000 blocks
    spmm_kernel<<<(BB * EE) / (4 * 8), 256>>>(rows, cols, vals, xw, out);
}

// round 4
// speedup vs baseline: 1.3749x; 1.3749x over previous
#include <cuda_runtime.h>
#include <cstdint>

// Problem constants (fixed by the reference)
#define BB 8
#define NN 10000
#define FF 256
#define HH 128
#define EE 320000

// Scratch for xw = dropout(x) @ W : [B, N, H] = 8*10000*128 floats = 41 MB
__device__ float g_xw[(size_t)BB * NN * HH];

__device__ __forceinline__ float to_tf32(float x) {
    float y;
    asm("cvt.rna.tf32.f32 %0, %1;" : "=f"(y) : "f"(x));
    return y;
}

__device__ __forceinline__ void mma_tf32(float* d, const uint32_t* a, const uint32_t* b) {
    asm volatile(
        "mma.sync.aligned.m16n8k8.row.col.f32.tf32.tf32.f32 "
        "{%0,%1,%2,%3}, {%4,%5,%6,%7}, {%8,%9}, {%0,%1,%2,%3};"
        : "+f"(d[0]), "+f"(d[1]), "+f"(d[2]), "+f"(d[3])
        : "r"(a[0]), "r"(a[1]), "r"(a[2]), "r"(a[3]), "r"(b[0]), "r"(b[1]));
}

// ---------------------------------------------------------------------------
// Kernel 0: zero the output (harness poisons it with 0xAA)
// ---------------------------------------------------------------------------
__global__ __launch_bounds__(256) void zero_kernel(float4* __restrict__ out) {
    size_t i = (size_t)blockIdx.x * blockDim.x + threadIdx.x;
    out[i] = make_float4(0.f, 0.f, 0.f, 0.f);
}

// ---------------------------------------------------------------------------
// Kernel 1: fused dropout + tf32 mma.sync GEMM
//   A = tf32(dropout(X))  [M=80000, K=256],  B = W  [K=256, N=128],  C = g_xw
// CTA tile 128x128, BK=32, 8 warps (4m x 2n), warp tile 32x64.
// As [m][k] pitch 36 (pitch%32==4 -> conflict-free A-frag LDS, 16B-aligned rows)
// Bs [k][n] pitch 136 (pitch%32==8 -> conflict-free B-frag LDS)
// Register-prefetch pipeline over a single smem buffer.
// ---------------------------------------------------------------------------
#define AP 36
#define BP 136

__global__ __launch_bounds__(256) void gemm_tf32_mma_kernel(
    const float* __restrict__ X, const float* __restrict__ U,
    const float* __restrict__ W, float* __restrict__ XW)
{
    __shared__ float As[128 * AP];   // 18432 B
    __shared__ float Bs[32 * BP];    // 17408 B

    const int tid  = threadIdx.x;
    const int lane = tid & 31;
    const int wid  = tid >> 5;
    const int wm   = wid & 3;        // 0..3 -> m offset wm*32
    const int wn   = wid >> 2;       // 0..1 -> n offset wn*64
    const int g    = lane >> 2;      // groupID 0..7
    const int t    = lane & 3;       // threadID-in-group 0..3
    const int mBase = blockIdx.x * 128;

    const float4* __restrict__ X4 = (const float4*)X;
    const float4* __restrict__ U4 = (const float4*)U;
    const float4* __restrict__ W4 = (const float4*)W;

    // Per-thread staging map. A: 1024 float4/chunk; B: 128 float4/chunk.
    // A: i-th piece: f4 = i*256+tid -> row = f4>>3 (0..127), q = f4&7 (k float4)
    // B: f4 = tid (first 128 threads... no: 128 float4 over 256 threads -> half)
    //    use f4b = tid, valid for tid<128? Instead: 128 f4 -> tid<128 loads 1.
    //    Simpler: every thread with tid<128: kk = tid>>2 is wrong. Map:
    //    f4b = tid (tid<128): kk = tid>>2 (0..31), nq = tid&3 ... that's 32*4=128 ✓
    //    W4 row stride = 32 float4 (128 floats). kk*32 + ... wait nq must span 0..31.
    //    Correct: Bs chunk is 32k x 128n = 4096 floats = 1024 float4?? 32*128=4096
    //    floats = 1024 float4. So 4 per thread, same as A.
    float acc[2][8][4];
#pragma unroll
    for (int mt = 0; mt < 2; ++mt)
#pragma unroll
        for (int nt = 0; nt < 8; ++nt)
#pragma unroll
            for (int j = 0; j < 4; ++j) acc[mt][nt][j] = 0.f;

    float4 xr[4], ur[4], wr[4];

    // preload chunk 0
#pragma unroll
    for (int i = 0; i < 4; ++i) {
        int f4  = i * 256 + tid;
        int row = f4 >> 3;
        int q   = f4 & 7;
        size_t gi = (size_t)(mBase + row) * 64 + q;
        xr[i] = X4[gi];
        ur[i] = U4[gi];
        int kk = f4 >> 5;        // 0..31
        int nq = f4 & 31;        // 0..31
        wr[i] = W4[(size_t)kk * 32 + nq];
    }

    for (int c = 0; c < 8; ++c) {
        __syncthreads();   // previous chunk's compute done; smem reusable
        // commit staged regs -> smem (dropout + tf32 on A, tf32 on B)
#pragma unroll
        for (int i = 0; i < 4; ++i) {
            int f4  = i * 256 + tid;
            int row = f4 >> 3;
            int q   = f4 & 7;
            float4 av;
            av.x = (ur[i].x > 0.5f) ? to_tf32(2.0f * xr[i].x) : 0.0f;
            av.y = (ur[i].y > 0.5f) ? to_tf32(2.0f * xr[i].y) : 0.0f;
            av.z = (ur[i].z > 0.5f) ? to_tf32(2.0f * xr[i].z) : 0.0f;
            av.w = (ur[i].w > 0.5f) ? to_tf32(2.0f * xr[i].w) : 0.0f;
            *(float4*)&As[row * AP + q * 4] = av;

            int kk = f4 >> 5;
            int nq = f4 & 31;
            float4 bv;
            bv.x = to_tf32(wr[i].x);
            bv.y = to_tf32(wr[i].y);
            bv.z = to_tf32(wr[i].z);
            bv.w = to_tf32(wr[i].w);
            *(float4*)&Bs[kk * BP + nq * 4] = bv;
        }
        __syncthreads();

        // prefetch next chunk
        if (c < 7) {
#pragma unroll
            for (int i = 0; i < 4; ++i) {
                int f4  = i * 256 + tid;
                int row = f4 >> 3;
                int q   = f4 & 7;
                size_t gi = (size_t)(mBase + row) * 64 + (size_t)(c + 1) * 8 + q;
                xr[i] = X4[gi];
                ur[i] = U4[gi];
                int kk = f4 >> 5;
                int nq = f4 & 31;
                wr[i] = W4[(size_t)((c + 1) * 32 + kk) * 32 + nq];
            }
        }

        // compute: 4 k-steps of k8
#pragma unroll
        for (int ks = 0; ks < 4; ++ks) {
            const int kb = ks * 8;
            uint32_t a[2][4];
#pragma unroll
            for (int mt = 0; mt < 2; ++mt) {
                int r0 = wm * 32 + mt * 16;
                a[mt][0] = __float_as_uint(As[(r0 + g) * AP + kb + t]);
                a[mt][1] = __float_as_uint(As[(r0 + g + 8) * AP + kb + t]);
                a[mt][2] = __float_as_uint(As[(r0 + g) * AP + kb + t + 4]);
                a[mt][3] = __float_as_uint(As[(r0 + g + 8) * AP + kb + t + 4]);
            }
            uint32_t b[8][2];
#pragma unroll
            for (int nt = 0; nt < 8; ++nt) {
                int n = wn * 64 + nt * 8 + g;
                b[nt][0] = __float_as_uint(Bs[(kb + t) * BP + n]);
                b[nt][1] = __float_as_uint(Bs[(kb + t + 4) * BP + n]);
            }
#pragma unroll
            for (int mt = 0; mt < 2; ++mt)
#pragma unroll
                for (int nt = 0; nt < 8; ++nt)
                    mma_tf32(acc[mt][nt], a[mt], b[nt]);
        }
    }

    // epilogue: thread (g,t) holds rows g,g+8 / cols 2t,2t+1 of each 16x8 tile
#pragma unroll
    for (int mt = 0; mt < 2; ++mt) {
#pragma unroll
        for (int nt = 0; nt < 8; ++nt) {
            size_t m0 = (size_t)(mBase + wm * 32 + mt * 16 + g);
            int n = wn * 64 + nt * 8 + 2 * t;
            *(float2*)&XW[m0 * HH + n] =
                make_float2(acc[mt][nt][0], acc[mt][nt][1]);
            *(float2*)&XW[(m0 + 8) * HH + n] =
                make_float2(acc[mt][nt][2], acc[mt][nt][3]);
        }
    }
}

// ---------------------------------------------------------------------------
// Kernel 2: SpMM scatter with vector atomics (unchanged).
// ---------------------------------------------------------------------------
__device__ __forceinline__ void red_add_v4(float* dst, float4 v) {
    asm volatile("red.global.add.v4.f32 [%0], {%1, %2, %3, %4};"
                 :: "l"(dst), "f"(v.x), "f"(v.y), "f"(v.z), "f"(v.w)
                 : "memory");
}

__global__ __launch_bounds__(256) void spmm_kernel(
    const int* __restrict__ rows, const int* __restrict__ cols,
    const float* __restrict__ vals, const float* __restrict__ xw,
    float* __restrict__ out)
{
    const int EPW = 4; // edges per warp
    const int warp = (blockIdx.x * blockDim.x + threadIdx.x) >> 5;
    const int lane = threadIdx.x & 31;

    long long e0 = (long long)warp * EPW;

    float4 contrib[EPW];
    float* dst[EPW];
#pragma unroll
    for (int i = 0; i < EPW; ++i) {
        long long e = e0 + i;
        int b = (int)(e / EE);
        int r = __ldg(&rows[e]);
        int c = __ldg(&cols[e]);
        float v = __ldg(&vals[e]);
        const float4* src = (const float4*)(xw + ((size_t)b * NN + c) * HH) + lane;
        float4 s = __ldg(src);
        contrib[i] = make_float4(v * s.x, v * s.y, v * s.z, v * s.w);
        dst[i] = out + ((size_t)b * NN + r) * HH + lane * 4;
    }
#pragma unroll
    for (int i = 0; i < EPW; ++i)
        red_add_v4(dst[i], contrib[i]);
}

// ---------------------------------------------------------------------------
// launch
// ---------------------------------------------------------------------------
extern "C" void kernel_launch(void* const* d_in, const int* in_sizes, int n_in,
                              void* d_out, int out_size) {
    const float* x    = (const float*)d_in[0];      // [8,10000,256] f32
    const float* u    = (const float*)d_in[1];      // [8,10000,256] f32
    const int*   rows = (const int*)d_in[2];        // [8,320000] int32
    const int*   cols = (const int*)d_in[3];        // [8,320000] int32
    const float* vals = (const float*)d_in[4];      // [8,320000] f32
    const float* w    = (const float*)d_in[5];      // [256,128] f32
    float* out = (float*)d_out;                     // [8,10000,128] f32

    float* xw;
    cudaGetSymbolAddress((void**)&xw, g_xw);

    // 0) zero the output
    zero_kernel<<<(BB * NN * HH / 4) / 256, 256>>>((float4*)out);

    // 1) fused dropout + tf32 mma GEMM: 625 tiles of 128 rows
    gemm_tf32_mma_kernel<<<(BB * NN) / 128, 256>>>(x, u, w, xw);

    // 2) SpMM scatter: 2.56M edges
    spmm_kernel<<<(BB * EE) / (4 * 8), 256>>>(rows, cols, vals, xw, out);
}